// round 4
// baseline (speedup 1.0000x reference)
#include <cuda_runtime.h>
#include <cuda_bf16.h>

// Problem constants
#define BB   64
#define LL   32
#define NT   64
#define TT   64
#define SS   128
#define VV   50000
#define EMB  512
#define SD   512
#define EPSF 1e-9f
#define NCELL 528           // L*(L+1)/2 per batch
#define MAXC  1984          // max cells per level = 64*31

// ----------------------------------------------------------------------------
// Persistent scratch (device globals; zero-initialized once at module load).
// chart_p upper halves (levels>=2) and level-32 tail rely on static zero-init
// and are never written -> deterministic across graph replays.
// ----------------------------------------------------------------------------
__device__ float g_chart_p[BB * NCELL * SS];          // 17 MB
__device__ float g_u      [BB * NCELL * SS];          // 17 MB
__device__ float g_chart_f[BB * NCELL * SD];          // 69 MB
__device__ float g_T      [BB * NCELL * 1024];        // 138 MB  (Lt | Rt)
__device__ float g_R      [276824064];                // 64*528*8192 ~ 1.03 GiB
__device__ float g_mass   [31 * MAXC];
__device__ float g_GT     [2][64 * 8192];             // GT[v][t][(a,s)]
__device__ float g_GsumT  [2][64 * 128];              // GsumT[v][t][s]
__device__ float g_W2     [512 * 1024];               // [k][j] j<512:Wm_top, else Wm_bot

__host__ __device__ __forceinline__ int triOff(int len) {
    return ((len - 1) * (66 - len)) >> 1;
}
__device__ __forceinline__ int cellIdx(int b, int i, int len) {
    return b * NCELL + triOff(len) + i;
}

// ----------------------------------------------------------------------------
// Prep kernels (cheap, rerun every replay for determinism)
// ----------------------------------------------------------------------------
__global__ void build_gt(const float* __restrict__ G) {
    int idx = blockIdx.x * 256 + threadIdx.x;           // 64*8192
    if (idx >= 64 * 8192) return;
    int t = idx >> 13, j = idx & 8191;
    int a = j >> 7, s = j & 127;
    const float* gp = G + a * 16384 + s * 128 + t;
    g_GT[0][idx] = gp[0];
    g_GT[1][idx] = gp[64];
}

__global__ void build_gsum(const float* __restrict__ G) {
    int idx = blockIdx.x * 256 + threadIdx.x;           // 2*64*128
    if (idx >= 2 * 64 * 128) return;
    int v = idx >> 13, t = (idx >> 7) & 63, s = idx & 127;
    const float* gp = G + s * 128 + v * 64 + t;
    float sum = 0.f;
    #pragma unroll 8
    for (int a = 0; a < 64; ++a) sum += gp[a * 16384];
    g_GsumT[v][t * 128 + s] = sum;
}

__global__ void build_w2(const float* __restrict__ Wm) {
    int idx = blockIdx.x * 256 + threadIdx.x;           // 512*1024
    if (idx >= 512 * 1024) return;
    int k = idx >> 10, j = idx & 1023;
    g_W2[idx] = (j < 512) ? Wm[k * 512 + j] : Wm[(512 + k) * 512 + (j - 512)];
}

// ----------------------------------------------------------------------------
// Level-1 preterminal distribution
// ----------------------------------------------------------------------------
__global__ void diag_kernel(const int* __restrict__ word,
                            const float* __restrict__ preterm) {
    int c = blockIdx.x;                  // 0..2047 = b*32+i
    int tid = threadIdx.x;               // 64 threads
    int w = word[c];
    float v = preterm[tid * VV + w];
    float s = v;
    #pragma unroll
    for (int o = 16; o; o >>= 1) s += __shfl_down_sync(0xffffffffu, s, o);
    __shared__ float red[2];
    if ((tid & 31) == 0) red[tid >> 5] = s;
    __syncthreads();
    float tot = red[0] + red[1] + EPSF;
    int b = c >> 5, i = c & 31;
    float* cp = g_chart_p + (long)cellIdx(b, i, 1) * SS;
    cp[tid]      = 0.f;
    cp[64 + tid] = v / tot;
}

// ----------------------------------------------------------------------------
// Generic tiled GEMM: C[r][j] = sum_k A[r][k] * B[k][j]  (+ optional relu+bias)
// 64x64 tile, BK=16, 256 threads, 4x4 micro-tile.
// Row r -> (b = r/n, i = r%n); addr = b*bs + i*is + cst. Optional gather rows.
// ----------------------------------------------------------------------------
__global__ void __launch_bounds__(256) gemm_k(
    const float* __restrict__ A, const float* __restrict__ Bm,
    float* __restrict__ C, int K, int N, int n,
    const int* __restrict__ gidx,
    int a_bs, int a_is, int a_cst,
    int c_bs, int c_is, int c_cst,
    const float* __restrict__ bias)
{
    __shared__ float As[16][64];
    __shared__ float Bs[16][64];
    int tid  = threadIdx.x;
    int row0 = blockIdx.y << 6, col0 = blockIdx.x << 6;

    int lr = tid >> 2, lk4 = (tid & 3) << 2;
    int r = row0 + lr;
    const float* Aptr;
    if (gidx) {
        Aptr = A + (long)gidx[r] * EMB + lk4;
    } else {
        int b = r / n, i = r - b * n;
        Aptr = A + (long)b * a_bs + (long)i * a_is + a_cst + lk4;
    }
    int bk = tid >> 4, bn4 = (tid & 15) << 2;
    const float* Bptr = Bm + (long)bk * N + col0 + bn4;

    int ty = tid >> 4, tx = tid & 15;
    float acc[4][4];
    #pragma unroll
    for (int ii = 0; ii < 4; ++ii)
        #pragma unroll
        for (int jj = 0; jj < 4; ++jj) acc[ii][jj] = 0.f;

    for (int k0 = 0; k0 < K; k0 += 16) {
        float4 av = *(const float4*)(Aptr + k0);
        float4 bv = *(const float4*)(Bptr + (long)k0 * N);
        if (k0) __syncthreads();
        As[lk4 + 0][lr] = av.x; As[lk4 + 1][lr] = av.y;
        As[lk4 + 2][lr] = av.z; As[lk4 + 3][lr] = av.w;
        *(float4*)&Bs[bk][bn4] = bv;
        __syncthreads();
        #pragma unroll
        for (int kk = 0; kk < 16; ++kk) {
            float4 af = *(const float4*)&As[kk][ty << 2];
            float4 bf = *(const float4*)&Bs[kk][tx << 2];
            float ar[4] = {af.x, af.y, af.z, af.w};
            float br[4] = {bf.x, bf.y, bf.z, bf.w};
            #pragma unroll
            for (int ii = 0; ii < 4; ++ii)
                #pragma unroll
                for (int jj = 0; jj < 4; ++jj)
                    acc[ii][jj] += ar[ii] * br[jj];
        }
    }

    int cc = col0 + (tx << 2);
    #pragma unroll
    for (int ii = 0; ii < 4; ++ii) {
        int rr = row0 + (ty << 2) + ii;
        int b = rr / n, i = rr - b * n;
        float* Cp = C + (long)b * c_bs + (long)i * c_is + c_cst + cc;
        float4 v = make_float4(acc[ii][0], acc[ii][1], acc[ii][2], acc[ii][3]);
        if (bias) {
            v.x = fmaxf(v.x + bias[cc + 0], 0.f);
            v.y = fmaxf(v.y + bias[cc + 1], 0.f);
            v.z = fmaxf(v.z + bias[cc + 2], 0.f);
            v.w = fmaxf(v.w + bias[cc + 3], 0.f);
        }
        *(float4*)Cp = v;
    }
}

// ----------------------------------------------------------------------------
// Scores: for each parent cell at level ln, accumulate over splits d:
//   scores[a] += dot64(lp_d, R[right_d, a, soff..]) ; mass_d = dot64(lp_d, u[right_d])
// then normalize and write chart_p.
// ----------------------------------------------------------------------------
__global__ void __launch_bounds__(256) scores_kernel(int ln, int n) {
    int c = blockIdx.x;
    int b = c / n, i = c - b * n;
    int tid = threadIdx.x;
    int a = tid >> 2, q = tid & 3;
    __shared__ float lp[64], us[64], red[2], sc[64];
    float acc = 0.f;

    for (int d = 1; d < ln; ++d) {
        int soff = (d == 1) ? 64 : 0;
        int rLen = ln - d;
        __syncthreads();
        if (tid < 64) {
            lp[tid] = g_chart_p[(long)cellIdx(b, i, d) * SS + soff + tid];
            us[tid] = g_u[(long)cellIdx(b, i + d, rLen) * SS + soff + tid];
        }
        __syncthreads();
        const float* Rrow = g_R + (long)cellIdx(b, i + d, rLen) * 8192
                                + a * 128 + soff + q * 16;
        const float* lps = lp + q * 16;
        float s = 0.f;
        #pragma unroll
        for (int j = 0; j < 16; j += 4) {
            float4 rv = *(const float4*)(Rrow + j);
            s += rv.x * lps[j] + rv.y * lps[j + 1] + rv.z * lps[j + 2] + rv.w * lps[j + 3];
        }
        acc += s;
        if (tid < 64) {
            float m = lp[tid] * us[tid];
            #pragma unroll
            for (int o = 16; o; o >>= 1) m += __shfl_down_sync(0xffffffffu, m, o);
            if ((tid & 31) == 0) red[tid >> 5] = m;
        }
        __syncthreads();
        if (tid == 0) g_mass[(d - 1) * MAXC + c] = red[0] + red[1];
    }

    acc += __shfl_down_sync(0xffffffffu, acc, 2);
    acc += __shfl_down_sync(0xffffffffu, acc, 1);
    if (q == 0) sc[a] = acc;
    __syncthreads();
    if (tid < 64) {
        float v = sc[tid];
        #pragma unroll
        for (int o = 16; o; o >>= 1) v += __shfl_down_sync(0xffffffffu, v, o);
        if ((tid & 31) == 0) red[tid >> 5] = v;
    }
    __syncthreads();
    float tot = red[0] + red[1] + EPSF;
    if (tid < 64)
        g_chart_p[(long)cellIdx(b, i, ln) * SS + tid] = sc[tid] / tot;
}

// ----------------------------------------------------------------------------
// Feature combine: f = sum_d w_d * relu(Lt[left_d] + Rt[right_d] + bm)
// ----------------------------------------------------------------------------
__global__ void __launch_bounds__(256) combine_kernel(int ln, int n,
                                                      const float* __restrict__ bm) {
    int c = blockIdx.x;
    int b = c / n, i = c - b * n;
    int tid = threadIdx.x;
    int D = ln - 1;
    __shared__ float w[32];
    __shared__ float tot_s;
    if (tid == 0) {
        float t = 0.f;
        for (int d = 0; d < D; ++d) t += g_mass[d * MAXC + c];
        tot_s = t + EPSF;
    }
    __syncthreads();
    if (tid < D) w[tid] = g_mass[tid * MAXC + c] / tot_s;
    __syncthreads();
    float bm0 = bm[tid], bm1 = bm[tid + 256];
    float f0 = 0.f, f1 = 0.f;
    for (int d = 1; d <= D; ++d) {
        const float* TL = g_T + (long)cellIdx(b, i, d) * 1024;
        const float* TR = g_T + (long)cellIdx(b, i + d, ln - d) * 1024 + 512;
        float wd = w[d - 1];
        f0 += wd * fmaxf(TL[tid]       + TR[tid]       + bm0, 0.f);
        f1 += wd * fmaxf(TL[tid + 256] + TR[tid + 256] + bm1, 0.f);
    }
    float* cf = g_chart_f + (long)cellIdx(b, i, ln) * SD;
    cf[tid]       = f0;
    cf[tid + 256] = f1;
}

// ----------------------------------------------------------------------------
// Root: out[b,:] = chart_f[b,0,L] * dot(chart_p[b,0,L], starts)
// ----------------------------------------------------------------------------
__global__ void root_kernel(const float* __restrict__ starts, float* __restrict__ out) {
    int b = blockIdx.x, tid = threadIdx.x;  // 128 threads
    const float* p = g_chart_p + (long)cellIdx(b, 0, LL) * SS;
    float v = p[tid] * starts[tid];
    #pragma unroll
    for (int o = 16; o; o >>= 1) v += __shfl_down_sync(0xffffffffu, v, o);
    __shared__ float red[4];
    if ((tid & 31) == 0) red[tid >> 5] = v;
    __syncthreads();
    float score = red[0] + red[1] + red[2] + red[3];
    const float* f = g_chart_f + (long)cellIdx(b, 0, LL) * SD;
    for (int h = tid; h < SD; h += 128) out[b * SD + h] = f[h] * score;
}

// ----------------------------------------------------------------------------
// Host driver
// ----------------------------------------------------------------------------
extern "C" void kernel_launch(void* const* d_in, const int* in_sizes, int n_in,
                              void* d_out, int out_size) {
    const int*   word    = (const int*)  d_in[0];
    const float* emb     = (const float*)d_in[1];
    const float* preterm = (const float*)d_in[2];
    const float* G       = (const float*)d_in[3];
    const float* starts  = (const float*)d_in[4];
    const float* Wp      = (const float*)d_in[5];
    const float* bp      = (const float*)d_in[6];
    const float* bm      = (const float*)d_in[8];
    const float* Wm      = (const float*)d_in[7];
    float* out = (float*)d_out;

    float *pP, *pU, *pF, *pT, *pR, *pGT, *pGsumT, *pW2;
    cudaGetSymbolAddress((void**)&pP,     g_chart_p);
    cudaGetSymbolAddress((void**)&pU,     g_u);
    cudaGetSymbolAddress((void**)&pF,     g_chart_f);
    cudaGetSymbolAddress((void**)&pT,     g_T);
    cudaGetSymbolAddress((void**)&pR,     g_R);
    cudaGetSymbolAddress((void**)&pGT,    g_GT);
    cudaGetSymbolAddress((void**)&pGsumT, g_GsumT);
    cudaGetSymbolAddress((void**)&pW2,    g_W2);

    // Prep
    build_gt  <<<(64 * 8192 + 255) / 256, 256>>>(G);
    build_gsum<<<(2 * 64 * 128 + 255) / 256, 256>>>(G);
    build_w2  <<<(512 * 1024 + 255) / 256, 256>>>(Wm);

    // Level 1
    diag_kernel<<<BB * LL, 64>>>(word, preterm);

    // feat0 = relu(emb[word] @ Wp + bp) -> chart_f level 1 (gather-A GEMM)
    {
        dim3 grid(SD >> 6, (BB * LL) >> 6);
        gemm_k<<<grid, 256>>>(emb, Wp, pF, EMB, SD, LL, word,
                              0, 0, 0,
                              NCELL * SD, SD, triOff(1) * SD,
                              bp);
    }
    // R, u for level-1 cells (t in [64,128))
    {
        int rows = BB * LL;
        dim3 gR(8192 >> 6, rows >> 6);
        gemm_k<<<gR, 256>>>(pP, pGT + 64 * 8192, pR, 64, 8192, LL, nullptr,
                            NCELL * SS, SS, triOff(1) * SS + 64,
                            NCELL * 8192, 8192, triOff(1) * 8192,
                            nullptr);
        dim3 gU(128 >> 6, rows >> 6);
        gemm_k<<<gU, 256>>>(pP, pGsumT + 8192, pU, 64, 128, LL, nullptr,
                            NCELL * SS, SS, triOff(1) * SS + 64,
                            NCELL * SS, SS, triOff(1) * SS,
                            nullptr);
        dim3 gT(1024 >> 6, rows >> 6);
        gemm_k<<<gT, 256>>>(pF, pW2, pT, SD, 1024, LL, nullptr,
                            NCELL * SD, SD, triOff(1) * SD,
                            NCELL * 1024, 1024, triOff(1) * 1024,
                            nullptr);
    }

    // Levels 2..32
    for (int ln = 2; ln <= LL; ++ln) {
        int nn = LL - ln + 1;
        int cells = BB * nn;
        scores_kernel <<<cells, 256>>>(ln, nn);
        combine_kernel<<<cells, 256>>>(ln, nn, bm);
        if (ln < LL) {
            dim3 gR(8192 >> 6, cells >> 6);
            gemm_k<<<gR, 256>>>(pP, pGT, pR, 64, 8192, nn, nullptr,
                                NCELL * SS, SS, triOff(ln) * SS,
                                NCELL * 8192, 8192, triOff(ln) * 8192,
                                nullptr);
            dim3 gU(128 >> 6, cells >> 6);
            gemm_k<<<gU, 256>>>(pP, pGsumT, pU, 64, 128, nn, nullptr,
                                NCELL * SS, SS, triOff(ln) * SS,
                                NCELL * SS, SS, triOff(ln) * SS,
                                nullptr);
            dim3 gT(1024 >> 6, cells >> 6);
            gemm_k<<<gT, 256>>>(pF, pW2, pT, SD, 1024, nn, nullptr,
                                NCELL * SD, SD, triOff(ln) * SD,
                                NCELL * 1024, 1024, triOff(ln) * 1024,
                                nullptr);
        }
    }

    // Root
    root_kernel<<<BB, 128>>>(starts, out);
}